// round 15
// baseline (speedup 1.0000x reference)
#include <cuda_runtime.h>
#include <cuda_bf16.h>

// DDA_PU_loss: loss = sum_pos((rec-dv)^2)*(1-a)/2 + sum_neg((rec-dv)^2)*a/2
// Inputs (metadata order):
//  0: drug_virus_reconstruct  float32 [8192*16384]
//  1: drug_virus              float32 [8192*16384]
//  2: drug_virus_mask         float32 (UNUSED by reference)
//  3: pos_x_index  int32 [524288]
//  4: pos_y_index  int32 [524288]
//  5: neg_x_index  int32 [2097152]
//  6: neg_y_index  int32 [2097152]
//  7: alpha        float32 [1]
// Output: float32 scalar.
//
// R13: R10's full-occupancy geometry (2048 blocks x 256 thr, 10 gathers/thr)
// + R11's fused last-block reduction (ticket counter, self-resetting).

#define KP_N_POS   524288
#define KP_LOG_NV  14          // N_VIRUS = 16384 = 1<<14
#define KP_BLOCKS  2048
#define KP_THREADS 256
// 2048*256 = 524288 threads; thread t handles pos[t] and neg[t + k*524288],
// k=0..3 -> exact coverage, 10 independent gathers per thread.

__device__ float    g_partials[KP_BLOCKS];
__device__ unsigned g_ticket = 0;

__global__ __launch_bounds__(KP_THREADS)
void dda_fused_kernel(const float* __restrict__ rec,
                      const float* __restrict__ dv,
                      const int* __restrict__ px,
                      const int* __restrict__ py,
                      const int* __restrict__ nx,
                      const int* __restrict__ ny,
                      const float* __restrict__ alpha_p,
                      float* __restrict__ out)
{
    const unsigned t = blockIdx.x * KP_THREADS + threadIdx.x;  // 0..524287

    // --- front-batch index loads (coalesced) ---
    unsigned off0 = ((unsigned)__ldg(&px[t]) << KP_LOG_NV)
                  +  (unsigned)__ldg(&py[t]);
    unsigned offs[4];
#pragma unroll
    for (int k = 0; k < 4; k++) {
        unsigned j = t + (unsigned)k * KP_N_POS;
        offs[k] = ((unsigned)__ldg(&nx[j]) << KP_LOG_NV)
                +  (unsigned)__ldg(&ny[j]);
    }

    // --- 10 independent random-coordinate gathers (front-batched) ---
    float r0 = __ldg(rec + off0), v0 = __ldg(dv + off0);
    float nr[4], nd[4];
#pragma unroll
    for (int k = 0; k < 4; k++) { nr[k] = __ldg(rec + offs[k]); nd[k] = __ldg(dv + offs[k]); }

    float d0 = r0 - v0;
    float ns = 0.0f;
#pragma unroll
    for (int k = 0; k < 4; k++) { float d = nr[k] - nd[k]; ns = fmaf(d, d, ns); }

    const float alpha = __ldg(alpha_p);
    float sum = fmaf((1.0f - alpha) * 0.5f * d0, d0, (alpha * 0.5f) * ns);

    // --- block reduce (fp32 tree; ~1280 O(1)-magnitude terms per block) ---
#pragma unroll
    for (int o = 16; o > 0; o >>= 1)
        sum += __shfl_down_sync(0xffffffffu, sum, o);

    __shared__ float warp_sums[KP_THREADS / 32];
    const int lane = threadIdx.x & 31;
    const int wrp  = threadIdx.x >> 5;
    if (lane == 0) warp_sums[wrp] = sum;
    __syncthreads();

    __shared__ bool is_last;
    if (threadIdx.x == 0) {
        float v = warp_sums[0];
#pragma unroll
        for (int i = 1; i < KP_THREADS / 32; i++) v += warp_sums[i];
        g_partials[blockIdx.x] = v;
        __threadfence();
        unsigned prev = atomicAdd(&g_ticket, 1u);
        is_last = (prev == KP_BLOCKS - 1);
    }
    __syncthreads();

    // --- last block folds the 2048 partials -> scalar (double, deterministic) ---
    if (is_last) {
        const volatile float* parts = g_partials;   // cross-SM data, bypass L1
        double v = 0.0;
#pragma unroll
        for (int k = 0; k < KP_BLOCKS / KP_THREADS; k++)   // 8 each
            v += (double)parts[threadIdx.x + k * KP_THREADS];

#pragma unroll
        for (int o = 16; o > 0; o >>= 1)
            v += __shfl_down_sync(0xffffffffu, v, o);

        __shared__ double dws[KP_THREADS / 32];
        if (lane == 0) dws[wrp] = v;
        __syncthreads();

        if (wrp == 0) {
            double s = (lane < KP_THREADS / 32) ? dws[lane] : 0.0;
#pragma unroll
            for (int o = 4; o > 0; o >>= 1)
                s += __shfl_down_sync(0xffu, s, o);
            if (lane == 0) {
                out[0] = (float)s;
                g_ticket = 0;   // reset for next graph replay
            }
        }
    }
}

extern "C" void kernel_launch(void* const* d_in, const int* in_sizes, int n_in,
                              void* d_out, int out_size)
{
    const float* rec     = (const float*)d_in[0];
    const float* dv      = (const float*)d_in[1];
    // d_in[2] = mask, unused (reference ignores it)
    const int*   px      = (const int*)d_in[3];
    const int*   py      = (const int*)d_in[4];
    const int*   nx      = (const int*)d_in[5];
    const int*   ny      = (const int*)d_in[6];
    const float* alpha_p = (const float*)d_in[7];
    float*       out     = (float*)d_out;

    dda_fused_kernel<<<KP_BLOCKS, KP_THREADS>>>(rec, dv, px, py, nx, ny, alpha_p, out);
}

// round 16
// speedup vs baseline: 1.0936x; 1.0936x over previous
#include <cuda_runtime.h>
#include <cuda_bf16.h>

// DDA_PU_loss: loss = sum_pos((rec-dv)^2)*(1-a)/2 + sum_neg((rec-dv)^2)*a/2
// Inputs (metadata order):
//  0: drug_virus_reconstruct  float32 [8192*16384]
//  1: drug_virus              float32 [8192*16384]
//  2: drug_virus_mask         float32 (UNUSED by reference)
//  3: pos_x_index  int32 [524288]
//  4: pos_y_index  int32 [524288]
//  5: neg_x_index  int32 [2097152]
//  6: neg_y_index  int32 [2097152]
//  7: alpha        float32 [1]
// Output: float32 scalar.
//
// R15 geometry (2048x256, fused last-block reduction) + gathers switched from
// the .nc path to ld.global.cg to test/avoid 128B L2-fill promotion, and
// vectorized int4 neg-index loads (thread t -> pos[t], neg[4t..4t+3]).

#define KP_N_POS   524288
#define KP_LOG_NV  14          // N_VIRUS = 16384 = 1<<14
#define KP_BLOCKS  2048
#define KP_THREADS 256
// 2048*256 = 524288 threads; thread t handles pos[t] and neg[4t..4t+3]
// -> exact coverage, 10 independent gathers per thread.

__device__ float    g_partials[KP_BLOCKS];
__device__ unsigned g_ticket = 0;

__device__ __forceinline__ float ld_cg(const float* p) {
    float v;
    asm("ld.global.cg.f32 %0, [%1];" : "=f"(v) : "l"(p));
    return v;
}

__global__ __launch_bounds__(KP_THREADS, 8)
void dda_fused_kernel(const float* __restrict__ rec,
                      const float* __restrict__ dv,
                      const int* __restrict__ px,
                      const int* __restrict__ py,
                      const int* __restrict__ nx,
                      const int* __restrict__ ny,
                      const float* __restrict__ alpha_p,
                      float* __restrict__ out)
{
    const unsigned t = blockIdx.x * KP_THREADS + threadIdx.x;  // 0..524287

    // --- index loads: 2x LDG.32 (pos) + 2x LDG.128 (neg), fully coalesced ---
    unsigned off0 = ((unsigned)__ldg(&px[t]) << KP_LOG_NV)
                  +  (unsigned)__ldg(&py[t]);

    const int4 nxv = __ldg((const int4*)nx + t);
    const int4 nyv = __ldg((const int4*)ny + t);
    unsigned offs[4];
    offs[0] = ((unsigned)nxv.x << KP_LOG_NV) + (unsigned)nyv.x;
    offs[1] = ((unsigned)nxv.y << KP_LOG_NV) + (unsigned)nyv.y;
    offs[2] = ((unsigned)nxv.z << KP_LOG_NV) + (unsigned)nyv.z;
    offs[3] = ((unsigned)nxv.w << KP_LOG_NV) + (unsigned)nyv.w;

    // --- 10 independent random gathers via LSU .cg path (front-batched) ---
    float r0 = ld_cg(rec + off0), v0 = ld_cg(dv + off0);
    float nr[4], nd[4];
#pragma unroll
    for (int k = 0; k < 4; k++) { nr[k] = ld_cg(rec + offs[k]); nd[k] = ld_cg(dv + offs[k]); }

    float d0 = r0 - v0;
    float ns = 0.0f;
#pragma unroll
    for (int k = 0; k < 4; k++) { float d = nr[k] - nd[k]; ns = fmaf(d, d, ns); }

    const float alpha = __ldg(alpha_p);
    float sum = fmaf((1.0f - alpha) * 0.5f * d0, d0, (alpha * 0.5f) * ns);

    // --- block reduce (fp32 tree; ~1280 O(1)-magnitude terms per block) ---
#pragma unroll
    for (int o = 16; o > 0; o >>= 1)
        sum += __shfl_down_sync(0xffffffffu, sum, o);

    __shared__ float warp_sums[KP_THREADS / 32];
    const int lane = threadIdx.x & 31;
    const int wrp  = threadIdx.x >> 5;
    if (lane == 0) warp_sums[wrp] = sum;
    __syncthreads();

    __shared__ bool is_last;
    if (threadIdx.x == 0) {
        float v = warp_sums[0];
#pragma unroll
        for (int i = 1; i < KP_THREADS / 32; i++) v += warp_sums[i];
        g_partials[blockIdx.x] = v;
        __threadfence();
        unsigned prev = atomicAdd(&g_ticket, 1u);
        is_last = (prev == KP_BLOCKS - 1);
    }
    __syncthreads();

    // --- last block folds the 2048 partials -> scalar (double, deterministic) ---
    if (is_last) {
        const volatile float* parts = g_partials;   // cross-SM data, bypass L1
        double v = 0.0;
#pragma unroll
        for (int k = 0; k < KP_BLOCKS / KP_THREADS; k++)   // 8 each
            v += (double)parts[threadIdx.x + k * KP_THREADS];

#pragma unroll
        for (int o = 16; o > 0; o >>= 1)
            v += __shfl_down_sync(0xffffffffu, v, o);

        __shared__ double dws[KP_THREADS / 32];
        if (lane == 0) dws[wrp] = v;
        __syncthreads();

        if (wrp == 0) {
            double s = (lane < KP_THREADS / 32) ? dws[lane] : 0.0;
#pragma unroll
            for (int o = 4; o > 0; o >>= 1)
                s += __shfl_down_sync(0xffu, s, o);
            if (lane == 0) {
                out[0] = (float)s;
                g_ticket = 0;   // reset for next graph replay
            }
        }
    }
}

extern "C" void kernel_launch(void* const* d_in, const int* in_sizes, int n_in,
                              void* d_out, int out_size)
{
    const float* rec     = (const float*)d_in[0];
    const float* dv      = (const float*)d_in[1];
    // d_in[2] = mask, unused (reference ignores it)
    const int*   px      = (const int*)d_in[3];
    const int*   py      = (const int*)d_in[4];
    const int*   nx      = (const int*)d_in[5];
    const int*   ny      = (const int*)d_in[6];
    const float* alpha_p = (const float*)d_in[7];
    float*       out     = (float*)d_out;

    dda_fused_kernel<<<KP_BLOCKS, KP_THREADS>>>(rec, dv, px, py, nx, ny, alpha_p, out);
}